// round 2
// baseline (speedup 1.0000x reference)
#include <cuda_runtime.h>
#include <math.h>

#define BATCH 256
#define DI    5120
#define RNK   160
#define NS    16
#define RX    192            // 160 (delta) + 16 (B) + 16 (C)

#define KS1   20             // split-K factor for GEMM1
#define KCH   (DI / KS1)     // 256
#define BT1   16             // batch tile GEMM1

#define BT2   16             // batch tile GEMM2
#define DCH   128            // d-chunk (threads) GEMM2

// ---- scratch (no dynamic allocation allowed) ----
__device__ float g_part[KS1 * BATCH * RX];   // GEMM1 split-K partials
__device__ float g_xd[BATCH * RX];           // [xd | Bp | C]
__device__ float g_dt[BATCH * DI];           // softplus(delta)
__device__ float g_negA[DI * NS];            // -exp(A_log)

// ---------------------------------------------------------------- prep
__global__ void k_prep(const float* __restrict__ A_log) {
    int i = blockIdx.x * blockDim.x + threadIdx.x;
    if (i < DI * NS) g_negA[i] = -expf(A_log[i]);
}

// ---------------------------------------------------------------- GEMM1
// out[b][r] = sum_k x[b][k] * W[k][r],  W = concat(W_delta, W_B, W_C) columns.
// Split-K partials; block = 192 threads (one per output column), BT1 batches.
__global__ void k_gemm1(const float* __restrict__ x,
                        const float* __restrict__ Wd,
                        const float* __restrict__ WB,
                        const float* __restrict__ WC) {
    __shared__ float xs[32 * BT1];          // [kk][bb]
    const int r  = threadIdx.x;             // 0..191
    const int b0 = blockIdx.x * BT1;
    const int k0 = blockIdx.y * KCH;

    const float* wptr; int wstr;
    if (r < 160)      { wptr = Wd + r;         wstr = 160; }
    else if (r < 176) { wptr = WB + (r - 160); wstr = 16;  }
    else              { wptr = WC + (r - 176); wstr = 16;  }
    wptr += (size_t)k0 * wstr;

    float acc[BT1];
#pragma unroll
    for (int i = 0; i < BT1; i++) acc[i] = 0.f;

    for (int ks = 0; ks < KCH; ks += 32) {
        __syncthreads();
        for (int i = r; i < 32 * BT1; i += RX) {
            int bb = i >> 5, kk = i & 31;
            xs[kk * BT1 + bb] = x[(size_t)(b0 + bb) * DI + k0 + ks + kk];
        }
        __syncthreads();
#pragma unroll
        for (int kk = 0; kk < 32; kk++) {
            float w = wptr[(size_t)(ks + kk) * wstr];
            const float4* xv4 = reinterpret_cast<const float4*>(xs + kk * BT1);
#pragma unroll
            for (int j = 0; j < BT1 / 4; j++) {
                float4 xv = xv4[j];
                acc[4*j+0] += xv.x * w;
                acc[4*j+1] += xv.y * w;
                acc[4*j+2] += xv.z * w;
                acc[4*j+3] += xv.w * w;
            }
        }
    }
    float* out = g_part + ((size_t)blockIdx.y * BATCH + b0) * RX + r;
#pragma unroll
    for (int bb = 0; bb < BT1; bb++) out[(size_t)bb * RX] = acc[bb];
}

// ---------------------------------------------------------------- reduce
__global__ void k_reduce() {
    int i = blockIdx.x * blockDim.x + threadIdx.x;
    if (i >= BATCH * RX) return;
    float s = 0.f;
#pragma unroll
    for (int ks = 0; ks < KS1; ks++) s += g_part[(size_t)ks * (BATCH * RX) + i];
    g_xd[i] = s;
}

// ---------------------------------------------------------------- GEMM2 + softplus
// dt[b][d] = softplus( sum_r xd[b][r] * W_dt[r][d] + b_dt[d] )
__global__ void k_gemm2(const float* __restrict__ Wdt,
                        const float* __restrict__ b_dt) {
    __shared__ float xds[RNK * BT2];        // [r][bb]  (10 KB)
    const int tid = threadIdx.x;            // 0..127
    const int d   = blockIdx.x * DCH + tid;
    const int b0  = blockIdx.y * BT2;

    for (int i = tid; i < RNK * BT2; i += DCH) {
        int bb = i / RNK, r = i % RNK;
        xds[r * BT2 + bb] = g_xd[(size_t)(b0 + bb) * RX + r];
    }
    __syncthreads();

    float acc[BT2];
#pragma unroll
    for (int i = 0; i < BT2; i++) acc[i] = 0.f;

    const float* wp = Wdt + d;
#pragma unroll 4
    for (int r = 0; r < RNK; r++) {
        float w = wp[(size_t)r * DI];
        const float4* xv4 = reinterpret_cast<const float4*>(xds + r * BT2);
#pragma unroll
        for (int j = 0; j < BT2 / 4; j++) {
            float4 xv = xv4[j];
            acc[4*j+0] += xv.x * w;
            acc[4*j+1] += xv.y * w;
            acc[4*j+2] += xv.z * w;
            acc[4*j+3] += xv.w * w;
        }
    }

    float bv = b_dt[d];
#pragma unroll
    for (int bb = 0; bb < BT2; bb++) {
        float z  = acc[bb] + bv;
        float sp = (z > 20.f) ? z : log1pf(expf(z));
        g_dt[(size_t)(b0 + bb) * DI + d] = sp;
    }
}

// ---------------------------------------------------------------- fused SSM readout
// y[b][d] = sum_n exp(dt * (-exp(A_log[d,n]))) * h[b,d,n] * C[b,n]
//           + x[b,d] * ( dt * dot(Bp[b,:], C[b,:]) + D[d] )
__global__ void k_ssm(const float* __restrict__ x,
                      const float* __restrict__ h,
                      const float* __restrict__ Dv,
                      float* __restrict__ y) {
    __shared__ float Bs[NS], Cs[NS];
    const int b = blockIdx.y;
    const int d = blockIdx.x * 256 + threadIdx.x;

    if (threadIdx.x < NS)
        Bs[threadIdx.x] = g_xd[(size_t)b * RX + 160 + threadIdx.x];
    else if (threadIdx.x < 2 * NS)
        Cs[threadIdx.x - NS] = g_xd[(size_t)b * RX + 176 + (threadIdx.x - NS)];
    __syncthreads();

    float dt = g_dt[(size_t)b * DI + d];
    float xv = x[(size_t)b * DI + d];

    float bc = 0.f;
#pragma unroll
    for (int n = 0; n < NS; n++) bc += Bs[n] * Cs[n];

    const float4* hp = reinterpret_cast<const float4*>(h + ((size_t)b * DI + d) * NS);
    const float4* ap = reinterpret_cast<const float4*>(g_negA + (size_t)d * NS);

    float acc = 0.f;
#pragma unroll
    for (int q = 0; q < NS / 4; q++) {
        float4 hv = hp[q];
        float4 av = ap[q];
        acc += __expf(dt * av.x) * hv.x * Cs[4*q+0];
        acc += __expf(dt * av.y) * hv.y * Cs[4*q+1];
        acc += __expf(dt * av.z) * hv.z * Cs[4*q+2];
        acc += __expf(dt * av.w) * hv.w * Cs[4*q+3];
    }

    y[(size_t)b * DI + d] = acc + xv * (dt * bc + Dv[d]);
}

// ----------------------------------------------------------------
extern "C" void kernel_launch(void* const* d_in, const int* in_sizes, int n_in,
                              void* d_out, int out_size) {
    const float* x    = (const float*)d_in[0];
    const float* h    = (const float*)d_in[1];
    const float* Wd   = (const float*)d_in[2];
    const float* Wdt  = (const float*)d_in[3];
    const float* bdt  = (const float*)d_in[4];
    const float* Alog = (const float*)d_in[5];
    const float* WB   = (const float*)d_in[6];
    const float* WC   = (const float*)d_in[7];
    const float* D    = (const float*)d_in[8];
    float* y = (float*)d_out;

    k_prep  <<<(DI * NS + 255) / 256, 256>>>(Alog);
    k_gemm1 <<<dim3(BATCH / BT1, KS1), RX>>>(x, Wd, WB, WC);
    k_reduce<<<(BATCH * RX + 255) / 256, 256>>>();
    k_gemm2 <<<dim3(DI / DCH, BATCH / BT2), DCH>>>(Wdt, bdt);
    k_ssm   <<<dim3(DI / 256, BATCH), 256>>>(x, h, D, y);
}

// round 3
// speedup vs baseline: 1.1948x; 1.1948x over previous
#include <cuda_runtime.h>
#include <math.h>

#define BATCH 256
#define DI    5120
#define RNK   160
#define NS    16
#define RX    192            // 160 (delta) + 16 (B) + 16 (C)

#define KS1   40             // split-K factor for GEMM1
#define KCH   (DI / KS1)     // 128
#define BT1   16             // batch tile GEMM1

#define BT2   8              // batch tile fused kernel
#define DCH   128            // d-chunk (threads) fused kernel

// ---- scratch (no dynamic allocation allowed) ----
__device__ float g_part[KS1 * BATCH * RX];   // GEMM1 split-K partials (7.9 MB)
__device__ float g_xd[BATCH * RX];           // [xd | Bp | C]

// ---------------------------------------------------------------- GEMM1
// out[b][r] = sum_k x[b][k] * W[k][r],  W = concat(W_delta, W_B, W_C) columns.
// Split-K partials; block = 192 threads (one per output column), BT1 batches.
__global__ void k_gemm1(const float* __restrict__ x,
                        const float* __restrict__ Wd,
                        const float* __restrict__ WB,
                        const float* __restrict__ WC) {
    __shared__ float xs[32 * BT1];          // [kk][bb]
    const int r  = threadIdx.x;             // 0..191
    const int b0 = blockIdx.x * BT1;
    const int k0 = blockIdx.y * KCH;

    const float* wptr; int wstr;
    if (r < 160)      { wptr = Wd + r;         wstr = 160; }
    else if (r < 176) { wptr = WB + (r - 160); wstr = 16;  }
    else              { wptr = WC + (r - 176); wstr = 16;  }
    wptr += (size_t)k0 * wstr;

    float acc[BT1];
#pragma unroll
    for (int i = 0; i < BT1; i++) acc[i] = 0.f;

    for (int ks = 0; ks < KCH; ks += 32) {
        __syncthreads();
        for (int i = r; i < 32 * BT1; i += RX) {
            int bb = i >> 5, kk = i & 31;
            xs[kk * BT1 + bb] = x[(size_t)(b0 + bb) * DI + k0 + ks + kk];
        }
        __syncthreads();
#pragma unroll
        for (int kk = 0; kk < 32; kk++) {
            float w = wptr[(size_t)(ks + kk) * wstr];
            const float4* xv4 = reinterpret_cast<const float4*>(xs + kk * BT1);
#pragma unroll
            for (int j = 0; j < BT1 / 4; j++) {
                float4 xv = xv4[j];
                acc[4*j+0] += xv.x * w;
                acc[4*j+1] += xv.y * w;
                acc[4*j+2] += xv.z * w;
                acc[4*j+3] += xv.w * w;
            }
        }
    }
    float* out = g_part + ((size_t)blockIdx.y * BATCH + b0) * RX + r;
#pragma unroll
    for (int bb = 0; bb < BT1; bb++) out[(size_t)bb * RX] = acc[bb];
}

// ---------------------------------------------------------------- reduce
__global__ void k_reduce() {
    int i = blockIdx.x * blockDim.x + threadIdx.x;
    if (i >= BATCH * RX) return;
    float s = 0.f;
#pragma unroll
    for (int ks = 0; ks < KS1; ks++) s += g_part[(size_t)ks * (BATCH * RX) + i];
    g_xd[i] = s;
}

// ---------------------------------------------------------------- fused GEMM2 + softplus + SSM
// dt[b][d] = softplus( sum_r xd[b][r] * W_dt[r][d] + b_dt[d] )
// y[b][d]  = sum_n exp(dt * -exp(A_log[d,n])) * h[b,d,n] * C[b,n]
//            + x[b,d] * ( dt * dot(Bp[b,:], C[b,:]) + D[d] )
__global__ void __launch_bounds__(DCH)
k_fused(const float* __restrict__ x,
        const float* __restrict__ h,
        const float* __restrict__ Wdt,
        const float* __restrict__ b_dt,
        const float* __restrict__ A_log,
        const float* __restrict__ Dv,
        float* __restrict__ y) {
    __shared__ float xds[RNK * BT2];        // [r][bb]  5 KB
    __shared__ float BC[BT2 * 2 * NS];      // per batch: B[16] | C[16]
    __shared__ float bcs[BT2];              // dot(B, C) per batch
    const int tid = threadIdx.x;            // 0..127
    const int d   = blockIdx.x * DCH + tid;
    const int b0  = blockIdx.y * BT2;

    for (int i = tid; i < RNK * BT2; i += DCH) {
        int bb = i / RNK, r = i % RNK;
        xds[r * BT2 + bb] = g_xd[(size_t)(b0 + bb) * RX + r];
    }
    for (int i = tid; i < BT2 * 2 * NS; i += DCH) {
        int bb = i >> 5, j = i & 31;
        BC[i] = g_xd[(size_t)(b0 + bb) * RX + 160 + j];
    }
    __syncthreads();

    if (tid < BT2) {
        float s = 0.f;
#pragma unroll
        for (int n = 0; n < NS; n++) s += BC[tid * 32 + n] * BC[tid * 32 + NS + n];
        bcs[tid] = s;
    }

    // ---- GEMM2: acc[bb] = sum_r xd[b0+bb][r] * Wdt[r][d]
    float acc[BT2];
#pragma unroll
    for (int i = 0; i < BT2; i++) acc[i] = 0.f;

    const float* wp = Wdt + d;
#pragma unroll 4
    for (int r = 0; r < RNK; r++) {
        float w = wp[(size_t)r * DI];
        const float4* xv4 = reinterpret_cast<const float4*>(xds + r * BT2);
        float4 x0 = xv4[0];
        float4 x1 = xv4[1];
        acc[0] += x0.x * w;  acc[1] += x0.y * w;
        acc[2] += x0.z * w;  acc[3] += x0.w * w;
        acc[4] += x1.x * w;  acc[5] += x1.y * w;
        acc[6] += x1.z * w;  acc[7] += x1.w * w;
    }

    float bv = b_dt[d];
    float dt[BT2];
#pragma unroll
    for (int bb = 0; bb < BT2; bb++) {
        float z = acc[bb] + bv;
        dt[bb] = (z > 20.f) ? z : log1pf(expf(z));
    }

    // ---- -exp(A_log[d][:]) into registers (reused across all BT2 batches)
    float na[NS];
    const float4* ap = reinterpret_cast<const float4*>(A_log + (size_t)d * NS);
#pragma unroll
    for (int q = 0; q < NS / 4; q++) {
        float4 a = ap[q];
        na[4*q+0] = -expf(a.x);
        na[4*q+1] = -expf(a.y);
        na[4*q+2] = -expf(a.z);
        na[4*q+3] = -expf(a.w);
    }
    float Dval = Dv[d];

    __syncthreads();   // bcs ready

    // ---- SSM readout per batch
#pragma unroll
    for (int bb = 0; bb < BT2; bb++) {
        const int b = b0 + bb;
        float xv = x[(size_t)b * DI + d];
        const float4* hp = reinterpret_cast<const float4*>(h + ((size_t)b * DI + d) * NS);
        const float* Cb = BC + bb * 32 + NS;
        float dtv = dt[bb];
        float a2 = 0.f;
#pragma unroll
        for (int q = 0; q < NS / 4; q++) {
            float4 hv = hp[q];
            a2 += __expf(dtv * na[4*q+0]) * hv.x * Cb[4*q+0];
            a2 += __expf(dtv * na[4*q+1]) * hv.y * Cb[4*q+1];
            a2 += __expf(dtv * na[4*q+2]) * hv.z * Cb[4*q+2];
            a2 += __expf(dtv * na[4*q+3]) * hv.w * Cb[4*q+3];
        }
        y[(size_t)b * DI + d] = a2 + xv * (dtv * bcs[bb] + Dval);
    }
}

// ----------------------------------------------------------------
extern "C" void kernel_launch(void* const* d_in, const int* in_sizes, int n_in,
                              void* d_out, int out_size) {
    const float* x    = (const float*)d_in[0];
    const float* h    = (const float*)d_in[1];
    const float* Wd   = (const float*)d_in[2];
    const float* Wdt  = (const float*)d_in[3];
    const float* bdt  = (const float*)d_in[4];
    const float* Alog = (const float*)d_in[5];
    const float* WB   = (const float*)d_in[6];
    const float* WC   = (const float*)d_in[7];
    const float* D    = (const float*)d_in[8];
    float* y = (float*)d_out;

    k_gemm1 <<<dim3(BATCH / BT1, KS1), RX>>>(x, Wd, WB, WC);
    k_reduce<<<(BATCH * RX + 255) / 256, 256>>>();
    k_fused <<<dim3(DI / DCH, BATCH / BT2), DCH>>>(x, h, Wdt, bdt, Alog, D, y);
}

// round 4
// speedup vs baseline: 1.2236x; 1.0241x over previous
#include <cuda_runtime.h>
#include <math.h>

#define BATCH 256
#define DI    5120
#define RNK   160
#define NS    16
#define RX    192            // 160 (delta) + 16 (B) + 16 (C)

#define KS1   40             // split-K factor for GEMM1
#define KCH   (DI / KS1)     // 128
#define BT1   16             // batch tile GEMM1
#define WCH   16             // w prefetch chunk GEMM1

#define BT2   8              // batch tile fused kernel
#define DCH   128            // d-chunk (threads) fused kernel
#define RCH   8              // Wdt prefetch chunk fused kernel

// ---- scratch (no dynamic allocation allowed) ----
__device__ float g_part[KS1 * BATCH * RX];   // GEMM1 split-K partials (7.9 MB)
__device__ float g_xd[BATCH * RX];           // [xd | Bp | C]
__device__ float g_negA[DI * NS];            // -exp(A_log)

// ---------------------------------------------------------------- prep
__global__ void k_prep(const float* __restrict__ A_log) {
    int i = blockIdx.x * blockDim.x + threadIdx.x;
    if (i < DI * NS) g_negA[i] = -expf(A_log[i]);
}

// ---------------------------------------------------------------- GEMM1
// out[b][r] = sum_k x[b][k] * W[k][r],  W = concat(W_delta, W_B, W_C) columns.
// Stage full x-tile (KCH x BT1) in smem; double-buffered register prefetch of w.
__global__ void __launch_bounds__(RX)
k_gemm1(const float* __restrict__ x,
        const float* __restrict__ Wd,
        const float* __restrict__ WB,
        const float* __restrict__ WC) {
    __shared__ float xs[KCH * BT1];         // [kk][bb]  8 KB
    const int r  = threadIdx.x;             // 0..191
    const int b0 = blockIdx.x * BT1;
    const int k0 = blockIdx.y * KCH;

    // stage x tile: x[b0+bb][k0+kk] -> xs[kk][bb]
    for (int i = r; i < KCH * BT1; i += RX) {
        int bb = i / KCH, kk = i % KCH;     // consecutive i -> consecutive kk (coalesced)
        xs[kk * BT1 + bb] = x[(size_t)(b0 + bb) * DI + k0 + kk];
    }

    const float* wptr; int wstr;
    if (r < 160)      { wptr = Wd + r;         wstr = 160; }
    else if (r < 176) { wptr = WB + (r - 160); wstr = 16;  }
    else              { wptr = WC + (r - 176); wstr = 16;  }
    wptr += (size_t)k0 * wstr;

    float acc[BT1];
#pragma unroll
    for (int i = 0; i < BT1; i++) acc[i] = 0.f;

    __syncthreads();

    float wbuf[2][WCH];
#pragma unroll
    for (int j = 0; j < WCH; j++) wbuf[0][j] = wptr[(size_t)j * wstr];

    for (int c = 0; c < KCH / WCH; c++) {
        const int cur = c & 1;
        if (c + 1 < KCH / WCH) {
            const float* wn = wptr + (size_t)(c + 1) * WCH * wstr;
#pragma unroll
            for (int j = 0; j < WCH; j++) wbuf[cur ^ 1][j] = wn[(size_t)j * wstr];
        }
        const int kbase = c * WCH;
#pragma unroll
        for (int j = 0; j < WCH; j++) {
            float w = wbuf[cur][j];
            const float4* xv4 = reinterpret_cast<const float4*>(xs + (kbase + j) * BT1);
#pragma unroll
            for (int q = 0; q < BT1 / 4; q++) {
                float4 xv = xv4[q];
                acc[4*q+0] += xv.x * w;
                acc[4*q+1] += xv.y * w;
                acc[4*q+2] += xv.z * w;
                acc[4*q+3] += xv.w * w;
            }
        }
    }

    float* out = g_part + ((size_t)blockIdx.y * BATCH + b0) * RX + r;
#pragma unroll
    for (int bb = 0; bb < BT1; bb++) out[(size_t)bb * RX] = acc[bb];
}

// ---------------------------------------------------------------- reduce
__global__ void k_reduce() {
    int i = blockIdx.x * blockDim.x + threadIdx.x;
    if (i >= BATCH * RX) return;
    float s = 0.f;
#pragma unroll
    for (int ks = 0; ks < KS1; ks++) s += g_part[(size_t)ks * (BATCH * RX) + i];
    g_xd[i] = s;
}

// ---------------------------------------------------------------- fused GEMM2 + softplus + SSM
__global__ void __launch_bounds__(DCH)
k_fused(const float* __restrict__ x,
        const float* __restrict__ h,
        const float* __restrict__ Wdt,
        const float* __restrict__ b_dt,
        const float* __restrict__ Dv,
        float* __restrict__ y) {
    __shared__ float xds[RNK * BT2];        // [r][bb]  5 KB
    __shared__ float BC[BT2 * 2 * NS];      // per batch: B[16] | C[16]
    __shared__ float bcs[BT2];              // dot(B, C) per batch
    const int tid = threadIdx.x;            // 0..127
    const int d   = blockIdx.x * DCH + tid;
    const int b0  = blockIdx.y * BT2;

    for (int i = tid; i < RNK * BT2; i += DCH) {
        int bb = i / RNK, r = i % RNK;
        xds[r * BT2 + bb] = g_xd[(size_t)(b0 + bb) * RX + r];
    }
    for (int i = tid; i < BT2 * 2 * NS; i += DCH) {
        int bb = i >> 5, j = i & 31;
        BC[i] = g_xd[(size_t)(b0 + bb) * RX + 160 + j];
    }
    __syncthreads();

    if (tid < BT2) {
        float s = 0.f;
#pragma unroll
        for (int n = 0; n < NS; n++) s += BC[tid * 32 + n] * BC[tid * 32 + NS + n];
        bcs[tid] = s;
    }

    // ---- GEMM2: acc[bb] = sum_r xd[b0+bb][r] * Wdt[r][d]
    // double-buffered register prefetch of Wdt column (chunks of RCH)
    float acc[BT2];
#pragma unroll
    for (int i = 0; i < BT2; i++) acc[i] = 0.f;

    const float* wp = Wdt + d;
    float wbuf[2][RCH];
#pragma unroll
    for (int j = 0; j < RCH; j++) wbuf[0][j] = wp[(size_t)j * DI];

    for (int c = 0; c < RNK / RCH; c++) {
        const int cur = c & 1;
        if (c + 1 < RNK / RCH) {
            const float* wn = wp + (size_t)(c + 1) * RCH * DI;
#pragma unroll
            for (int j = 0; j < RCH; j++) wbuf[cur ^ 1][j] = wn[(size_t)j * DI];
        }
        const int rbase = c * RCH;
#pragma unroll
        for (int j = 0; j < RCH; j++) {
            float w = wbuf[cur][j];
            const float4* xv4 = reinterpret_cast<const float4*>(xds + (rbase + j) * BT2);
            float4 x0 = xv4[0];
            float4 x1 = xv4[1];
            acc[0] += x0.x * w;  acc[1] += x0.y * w;
            acc[2] += x0.z * w;  acc[3] += x0.w * w;
            acc[4] += x1.x * w;  acc[5] += x1.y * w;
            acc[6] += x1.z * w;  acc[7] += x1.w * w;
        }
    }

    float bv = b_dt[d];
    float dt[BT2];
#pragma unroll
    for (int bb = 0; bb < BT2; bb++) {
        float z = acc[bb] + bv;
        dt[bb] = (z > 20.f) ? z : log1pf(expf(z));
    }

    // ---- -exp(A_log[d][:]) from precomputed table (L2-resident)
    float na[NS];
    const float4* ap = reinterpret_cast<const float4*>(g_negA + (size_t)d * NS);
#pragma unroll
    for (int q = 0; q < NS / 4; q++) {
        float4 a = ap[q];
        na[4*q+0] = a.x; na[4*q+1] = a.y; na[4*q+2] = a.z; na[4*q+3] = a.w;
    }
    float Dval = Dv[d];

    // ---- x values for all batches up front (MLP)
    float xv[BT2];
#pragma unroll
    for (int bb = 0; bb < BT2; bb++) xv[bb] = x[(size_t)(b0 + bb) * DI + d];

    __syncthreads();   // bcs ready

    // ---- SSM readout: q outer, all batches' h loads issued back-to-back (MLP=BT2)
    float a2[BT2];
#pragma unroll
    for (int bb = 0; bb < BT2; bb++) a2[bb] = 0.f;

    const float4* hp = reinterpret_cast<const float4*>(h + ((size_t)b0 * DI + d) * NS);
    const size_t hstride4 = (size_t)DI * NS / 4;   // float4 stride between batches

#pragma unroll
    for (int q = 0; q < NS / 4; q++) {
        float4 hv[BT2];
#pragma unroll
        for (int bb = 0; bb < BT2; bb++) hv[bb] = hp[(size_t)bb * hstride4 + q];
#pragma unroll
        for (int bb = 0; bb < BT2; bb++) {
            const float* Cb = BC + bb * 32 + NS;
            float dtv = dt[bb];
            a2[bb] += __expf(dtv * na[4*q+0]) * hv[bb].x * Cb[4*q+0];
            a2[bb] += __expf(dtv * na[4*q+1]) * hv[bb].y * Cb[4*q+1];
            a2[bb] += __expf(dtv * na[4*q+2]) * hv[bb].z * Cb[4*q+2];
            a2[bb] += __expf(dtv * na[4*q+3]) * hv[bb].w * Cb[4*q+3];
        }
    }

#pragma unroll
    for (int bb = 0; bb < BT2; bb++)
        y[(size_t)(b0 + bb) * DI + d] = a2[bb] + xv[bb] * (dt[bb] * bcs[bb] + Dval);
}

// ----------------------------------------------------------------
extern "C" void kernel_launch(void* const* d_in, const int* in_sizes, int n_in,
                              void* d_out, int out_size) {
    const float* x    = (const float*)d_in[0];
    const float* h    = (const float*)d_in[1];
    const float* Wd   = (const float*)d_in[2];
    const float* Wdt  = (const float*)d_in[3];
    const float* bdt  = (const float*)d_in[4];
    const float* Alog = (const float*)d_in[5];
    const float* WB   = (const float*)d_in[6];
    const float* WC   = (const float*)d_in[7];
    const float* D    = (const float*)d_in[8];
    float* y = (float*)d_out;

    k_prep  <<<(DI * NS + 255) / 256, 256>>>(Alog);
    k_gemm1 <<<dim3(BATCH / BT1, KS1), RX>>>(x, Wd, WB, WC);
    k_reduce<<<(BATCH * RX + 255) / 256, 256>>>();
    k_fused <<<dim3(DI / DCH, BATCH / BT2), DCH>>>(x, h, Wdt, bdt, D, y);
}